// round 16
// baseline (speedup 1.0000x reference)
#include <cuda_runtime.h>
#include <cuda_bf16.h>
#include <cstdint>
#include <math.h>

// Problem constants
#define IN_DIM 44
#define H      128
#define H4     512
#define NL     4
#define TDEC   50
#define BATCH  2048
#define SEQ    200

#define TBS 16
#define TBU 14
#define RBLK ((BATCH + TBU - 1) / TBU)   // 147 blocks
#define NROWS (SEQ * BATCH)
#define MT64  (NROWS / 64)
#define GBX   74

typedef unsigned long long ull;
typedef __nv_bfloat16 bf16;

// ---------------------------------------------------------------------------
// Device scratch
// ---------------------------------------------------------------------------
__device__ float g_Xg[(long)NROWS * H4];
__device__ bf16  g_ysH[(long)NROWS * H];
__device__ bf16  g_ysL[(long)NROWS * H];
__device__ bf16  g_x0H[(long)NROWS * 48];
__device__ bf16  g_x0L[(long)NROWS * 48];
__device__ float g_h[NL * BATCH * H];
__device__ float g_c[NL * BATCH * H];
__device__ float g_encBP[NL * H4];
__device__ float g_decBP[NL * H4];
__device__ float g_fcT[H * IN_DIM];
// bf16 hi/lo GEMM weight planes, gate-permuted [n][k]
__device__ bf16 g_W0H[512 * 48];
__device__ bf16 g_W0L[512 * 48];
__device__ bf16 g_WRH[3 * 512 * 128];
__device__ bf16 g_WRL[3 * 512 * 128];
// fragment-major bf16 hi/lo weight planes for mma recurrences
__device__ ull g_eWhFH[NL * 16384];
__device__ ull g_eWhFL[NL * 16384];
__device__ ull g_dWhFH[NL * 16384];
__device__ ull g_dWhFL[NL * 16384];
__device__ ull g_dWiFH[3 * 16384];
__device__ ull g_dWiFL[3 * 16384];
__device__ ull g_dWi0FH[6144];
__device__ ull g_dWi0FL[6144];

// ---------------------------------------------------------------------------
// helpers
// ---------------------------------------------------------------------------
__device__ __forceinline__ float tanha(float x) {
    float y; asm("tanh.approx.f32 %0, %1;" : "=f"(y) : "f"(x)); return y;
}
__device__ __forceinline__ float sigf(float x) {
    return 0.5f * tanha(0.5f * x) + 0.5f;
}

__device__ __forceinline__ void cp16(unsigned int dst, const void* src) {
    asm volatile("cp.async.ca.shared.global [%0], [%1], 16;"
                 :: "r"(dst), "l"(src));
}
__device__ __forceinline__ void cp_commit() {
    asm volatile("cp.async.commit_group;");
}
__device__ __forceinline__ void cp_wait0() {
    asm volatile("cp.async.wait_group 0;");
}

#define MMA_BF16(d, a, b)                                                     \
    asm volatile(                                                             \
        "mma.sync.aligned.m16n8k16.row.col.f32.bf16.bf16.f32 "                \
        "{%0,%1,%2,%3}, {%4,%5,%6,%7}, {%8,%9}, {%0,%1,%2,%3};"               \
        : "+f"((d)[0]), "+f"((d)[1]), "+f"((d)[2]), "+f"((d)[3])              \
        : "r"((a)[0]), "r"((a)[1]), "r"((a)[2]), "r"((a)[3]),                 \
          "r"((b)[0]), "r"((b)[1]))

#define LDSM4(r, addr)                                                        \
    asm volatile("ldmatrix.sync.aligned.m8n8.x4.shared.b16 "                  \
        "{%0,%1,%2,%3}, [%4];"                                                \
        : "=r"((r)[0]), "=r"((r)[1]), "=r"((r)[2]), "=r"((r)[3])              \
        : "r"(addr))

__device__ __forceinline__ void split_bf16(float v, bf16& h, bf16& l) {
    h = __float2bfloat16_rn(v);
    l = __float2bfloat16_rn(v - __bfloat162float(h));
}

// ---------------------------------------------------------------------------
// Prep kernel A (merged): biases/fcT + GEMM weight hi/lo planes
// ---------------------------------------------------------------------------
__global__ void k_wconv(const float* __restrict__ enc_b, const float* __restrict__ dec_b,
                        const float* __restrict__ fc_W,
                        const float* __restrict__ Wih0, const float* __restrict__ WihR,
                        float* __restrict__ encBP, float* __restrict__ decBP,
                        float* __restrict__ fcT,
                        bf16* __restrict__ W0H, bf16* __restrict__ W0L,
                        bf16* __restrict__ WRH, bf16* __restrict__ WRL) {
    int job = blockIdx.y;
    int i = blockIdx.x * 256 + threadIdx.x;
    if (job == 0) {
        if (i < 2048) {
            int l = i >> 9, n = i & 511;
            encBP[i] = enc_b[l * 512 + ((n & 3) * 128 + (n >> 2))];
        } else if (i < 4096) {
            int i2 = i - 2048;
            int l = i2 >> 9, n = i2 & 511;
            decBP[i2] = dec_b[l * 512 + ((n & 3) * 128 + (n >> 2))];
        } else if (i < 4096 + H * IN_DIM) {
            int i2 = i - 4096;
            int k = i2 / IN_DIM, j = i2 - k * IN_DIM;
            fcT[i2] = fc_W[j * H + k];
        }
    } else if (job == 1) {
        if (i < 512 * 48) {
            int n = i / 48, k = i - n * 48;
            float w = 0.f;
            if (k < IN_DIM) w = Wih0[((n & 3) * 128 + (n >> 2)) * IN_DIM + k];
            split_bf16(w, W0H[i], W0L[i]);
        }
    } else {
        int r = job - 2;
        if (i < 512 * 128) {
            int n = i >> 7, k = i & 127;
            float w = WihR[(long)r * 512 * 128 + ((n & 3) * 128 + (n >> 2)) * 128 + k];
            split_bf16(w, WRH[(long)r * 512 * 128 + i], WRL[(long)r * 512 * 128 + i]);
        }
    }
}

// ---------------------------------------------------------------------------
// Prep kernel B: gather x -> hi/lo bf16 [row][48]
// ---------------------------------------------------------------------------
__global__ void k_xconv(const float* __restrict__ x,
                        bf16* __restrict__ XH, bf16* __restrict__ XL) {
    for (long i = (long)blockIdx.x * 256 + threadIdx.x; i < (long)NROWS * 48;
         i += (long)gridDim.x * 256) {
        int row = (int)(i / 48), k = (int)(i - (long)row * 48);
        int t = row >> 11, b = row & 2047;
        float v = (k < IN_DIM) ? x[((long)b * SEQ + t) * IN_DIM + k] : 0.f;
        split_bf16(v, XH[i], XL[i]);
    }
}

// ---------------------------------------------------------------------------
// Prep kernel C: generalized fragment builder.
// ---------------------------------------------------------------------------
struct FJob { const float* s; ull* fh; ull* fl; int ksteps; int ksrc; };
struct FJobs { FJob j[12]; int n; };

__global__ void k_fragb(FJobs jobs) {
    int job = blockIdx.y;
    if (job >= jobs.n) return;
    FJob J = jobs.j[job];
    int e = blockIdx.x * 256 + threadIdx.x;
    int tot = 64 * J.ksteps * 32 * 2;
    if (e >= tot) return;
    int fi = e >> 1, jj = e & 1;
    int lane = fi & 31;
    int rest = fi >> 5;
    int s = rest % J.ksteps;
    int T = rest / J.ksteps;
    int n = T * 8 + (lane >> 2);
    int k = s * 16 + (lane & 3) * 2 + jj * 8;
    int row = (n & 3) * 128 + (n >> 2);
    float v0 = (k < J.ksrc) ? J.s[(long)row * J.ksrc + k] : 0.f;
    float v1 = (k + 1 < J.ksrc) ? J.s[(long)row * J.ksrc + k + 1] : 0.f;
    bf16 h0, l0, h1, l1;
    split_bf16(v0, h0, l0);
    split_bf16(v1, h1, l1);
    __nv_bfloat162 ph; ph.x = h0; ph.y = h1;
    __nv_bfloat162 pl; pl.x = l0; pl.y = l1;
    ((uint32_t*)J.fh)[e] = *(uint32_t*)&ph;
    ((uint32_t*)J.fl)[e] = *(uint32_t*)&pl;
}

// ---------------------------------------------------------------------------
// Persistent weight-resident split-bf16 tensor-core GEMM.
// R16: N=128 per block, grid (74, 4), 256 threads, single-buffered A ->
// ~44/105 KB smem -> 2 blocks/SM (mutual latency hiding).
// 8 warps = 2(M) x 4(N); warp tile 32x32.
// ---------------------------------------------------------------------------
template <int K>
__global__ void __launch_bounds__(256, 2)
k_mmagemm(const bf16* __restrict__ AH, const bf16* __restrict__ AL,
          const bf16* __restrict__ WH, const bf16* __restrict__ WL,
          const float* __restrict__ biasP, float* __restrict__ out) {
    extern __shared__ char smc[];
    const int KSTEPS = K / 16;
    const int ROWB = (K + 8) * 2;
    const int BSP  = 128 * ROWB;           // one B split plane (N=128)
    const int ASP2 = 64 * ROWB;            // one A split plane
    const int CPR  = K / 8;

    char* Bb = smc;                        // [2 split][128][ROWB]
    char* Ab = smc + 2 * BSP;              // [2 split][64][ROWB] (single buf)
    float* bias_s = (float*)(smc + 2 * BSP + 2 * ASP2);

    const int tid = threadIdx.x;
    const int n0 = blockIdx.y * 128;
    const int w = tid >> 5, lane = tid & 31;
    const int wm = w >> 2, wn = w & 3;     // 2 x 4 warp grid, warp tile 32x32
    const int ar = lane >> 2, ac = (lane & 3) * 2;
    const int li = lane & 7, lq = lane >> 3;
    const int aoff = (li + (lq & 1) * 8) * ROWB + (lq >> 1) * 16;
    const int boff = (li + (lq >> 1) * 8) * ROWB + (lq & 1) * 16;

    const unsigned Bb_s = (unsigned)__cvta_generic_to_shared(Bb);
    const unsigned Ab_s = (unsigned)__cvta_generic_to_shared(Ab);

    if (tid < 128) bias_s[tid] = biasP[n0 + tid];

    // ---- stage B (resident, once) ----
    {
        const int total = 2 * 128 * CPR;
        for (int i = tid; i < total; i += 256) {
            int split = i / (128 * CPR);
            int rem = i - split * 128 * CPR;
            int n = rem / CPR, ch = rem - n * CPR;
            const bf16* src = (split ? WL : WH) + (long)(n0 + n) * K + ch * 8;
            unsigned dst = (unsigned)__cvta_generic_to_shared(
                Bb + split * BSP + n * ROWB + ch * 16);
            cp16(dst, src);
        }
        cp_commit();
    }

    for (int mt = blockIdx.x; mt < MT64; mt += GBX) {
        // ---- stage A tile (single buffer) ----
        {
            const int total = 2 * 64 * CPR;
            for (int i = tid; i < total; i += 256) {
                int split = i / (64 * CPR);
                int rem = i - split * 64 * CPR;
                int row = rem / CPR, ch = rem - row * CPR;
                const bf16* src = (split ? AL : AH) + (long)(mt * 64 + row) * K + ch * 8;
                unsigned dst = (unsigned)__cvta_generic_to_shared(
                    Ab + split * ASP2 + row * ROWB + ch * 16);
                cp16(dst, src);
            }
            cp_commit();
        }
        cp_wait0();
        __syncthreads();

        float acc[2][4][4];
#pragma unroll
        for (int mi = 0; mi < 2; ++mi)
#pragma unroll
            for (int ni = 0; ni < 4; ++ni)
#pragma unroll
                for (int q = 0; q < 4; ++q) acc[mi][ni][q] = 0.f;

#pragma unroll
        for (int ks = 0; ks < KSTEPS; ++ks) {
            const int kb2 = ks * 32;
            uint32_t ah[2][4], al[2][4];
#pragma unroll
            for (int mi = 0; mi < 2; ++mi) {
                unsigned base = Ab_s + (wm * 32 + mi * 16) * ROWB + kb2 + aoff;
                LDSM4(ah[mi], base);
                LDSM4(al[mi], base + ASP2);
            }
            uint32_t bhf[2][4], blf[2][4];
#pragma unroll
            for (int p = 0; p < 2; ++p) {
                unsigned nb = Bb_s + (wn * 32 + p * 16) * ROWB + kb2 + boff;
                LDSM4(bhf[p], nb);
                LDSM4(blf[p], nb + BSP);
            }
#pragma unroll
            for (int p = 0; p < 2; ++p) {
#pragma unroll
                for (int hh = 0; hh < 2; ++hh) {
                    int ni = p * 2 + hh;
                    uint32_t* bH = &bhf[p][hh * 2];
                    uint32_t* bL = &blf[p][hh * 2];
                    MMA_BF16(acc[0][ni], ah[0], bH);
                    MMA_BF16(acc[1][ni], ah[1], bH);
                    MMA_BF16(acc[0][ni], ah[0], bL);
                    MMA_BF16(acc[1][ni], ah[1], bL);
                    MMA_BF16(acc[0][ni], al[0], bH);
                    MMA_BF16(acc[1][ni], al[1], bH);
                }
            }
        }

        const int m0 = mt * 64;
#pragma unroll
        for (int mi = 0; mi < 2; ++mi) {
            int r = m0 + wm * 32 + mi * 16 + ar;
#pragma unroll
            for (int ni = 0; ni < 4; ++ni) {
                int cl = wn * 32 + ni * 8 + ac;
                float b0 = bias_s[cl], b1 = bias_s[cl + 1];
                float2 v0 = { acc[mi][ni][0] + b0, acc[mi][ni][1] + b1 };
                float2 v1 = { acc[mi][ni][2] + b0, acc[mi][ni][3] + b1 };
                *(float2*)&out[(long)r * H4 + n0 + cl] = v0;
                *(float2*)&out[(long)(r + 8) * H4 + n0 + cl] = v1;
            }
        }
        __syncthreads();   // all reads of A done before next tile overwrites
    }
}

// ---------------------------------------------------------------------------
// Tensor-core encoder recurrence (unchanged from R15)
// ---------------------------------------------------------------------------
#define AROWB 272
#define ASPL  (16 * AROWB)
#define BFRAG_BYTES 131072
#define GST   520
#define XROW  520
#define LSTM_MMA_SMEM (BFRAG_BYTES + 4 * ASPL + 16 * GST * 4 + 16 * XROW * 4)

template <bool WRITE_YS>
__global__ void __launch_bounds__(256, 1)
k_lstm_mma(const ull* __restrict__ FH, const ull* __restrict__ FL,
           bf16* __restrict__ ysH, bf16* __restrict__ ysL,
           float* __restrict__ hfin, float* __restrict__ cfin) {
    extern __shared__ char smc[];
    ull* BhF = (ull*)smc;
    char* As = smc + BFRAG_BYTES;
    float* gates = (float*)(As + 4 * ASPL);
    float* xgb = gates + 16 * GST;

    const int tid = threadIdx.x;
    const int w = tid >> 5, lane = tid & 31;
    const int li = lane & 7, lq = lane >> 3;
    const int aoff = (li + (lq & 1) * 8) * AROWB + (lq >> 1) * 16;
    const int ar = lane >> 2, ac = (lane & 3) * 2;
    const int cc = w * 16 + (lane & 15);
    const int hb = lane >> 4;
    const int b0 = blockIdx.x * TBU;

    ull flr[64];
#pragma unroll
    for (int i = 0; i < 64; ++i)
        flr[i] = FL[((w * 8 + (i >> 3)) * 8 + (i & 7)) * 32 + lane];

    for (int i = tid; i < 16384; i += 256) BhF[i] = FH[i];
    for (int i = tid; i < 2 * ASPL / 4; i += 256) ((float*)As)[i] = 0.f;

    float c_reg[8], hlast[8];
    int gbc[8]; bool vld[8];
#pragma unroll
    for (int i = 0; i < 8; ++i) {
        c_reg[i] = 0.f; hlast[i] = 0.f;
        int b = hb * 8 + i;
        int gb = b0 + b;
        gbc[i] = gb < BATCH ? gb : BATCH - 1;
        vld[i] = (b < TBU) && (gb < BATCH);
    }

    {
        const float* xg0 = g_Xg + 4 * cc;
#pragma unroll
        for (int i = 0; i < 8; ++i) {
            unsigned dst = (unsigned)__cvta_generic_to_shared(
                &xgb[(hb * 8 + i) * XROW + 4 * cc]);
            cp16(dst, xg0 + (long)gbc[i] * H4);
        }
        cp_commit();
        cp_wait0();
    }
    __syncthreads();

    const unsigned As_s = (unsigned)__cvta_generic_to_shared(As);

    for (int t = 0; t < SEQ; ++t) {
        const unsigned Ab = As_s + (t & 1) * (2 * ASPL);
        float acc[8][4];
#pragma unroll
        for (int ni = 0; ni < 8; ++ni)
#pragma unroll
            for (int q = 0; q < 4; ++q) acc[ni][q] = 0.f;

#pragma unroll
        for (int s = 0; s < 8; ++s) {
            uint32_t ah[4], al[4];
            LDSM4(ah, Ab + s * 32 + aoff);
            LDSM4(al, Ab + ASPL + s * 32 + aoff);
#pragma unroll
            for (int ni = 0; ni < 8; ++ni) {
                int fi = ((w * 8 + ni) * 8 + s) * 32 + lane;
                ull bh8 = BhF[fi];
                ull bl8 = flr[ni * 8 + s];
                uint32_t bh[2] = { (uint32_t)bh8, (uint32_t)(bh8 >> 32) };
                uint32_t bl[2] = { (uint32_t)bl8, (uint32_t)(bl8 >> 32) };
                MMA_BF16(acc[ni], ah, bh);
                MMA_BF16(acc[ni], ah, bl);
                MMA_BF16(acc[ni], al, bh);
            }
        }
#pragma unroll
        for (int ni = 0; ni < 8; ++ni) {
            int n0 = w * 64 + ni * 8 + ac;
            float2 v0 = { acc[ni][0], acc[ni][1] };
            float2 v1 = { acc[ni][2], acc[ni][3] };
            *(float2*)&gates[ar * GST + n0] = v0;
            *(float2*)&gates[(ar + 8) * GST + n0] = v1;
        }
        __syncwarp();
        cp_wait0();
        char* An = As + (((t + 1) & 1)) * (2 * ASPL);
#pragma unroll
        for (int i = 0; i < 8; ++i) {
            int b = hb * 8 + i;
            float4 g4 = *(const float4*)&gates[b * GST + 4 * cc];
            float4 x4 = *(const float4*)&xgb[b * XROW + 4 * cc];
            float gi = g4.x + x4.x, gf = g4.y + x4.y;
            float gg = g4.z + x4.z, go = g4.w + x4.w;
            float cn = sigf(gf) * c_reg[i] + sigf(gi) * tanha(gg);
            c_reg[i] = cn;
            float hn = sigf(go) * tanha(cn);
            hlast[i] = hn;
            bf16 hh, hl;
            split_bf16(hn, hh, hl);
            *(bf16*)(An + b * AROWB + cc * 2) = hh;
            *(bf16*)(An + ASPL + b * AROWB + cc * 2) = hl;
            if (WRITE_YS && vld[i]) {
                long idx = ((long)t * BATCH + b0 + b) * H + cc;
                ysH[idx] = hh;
                ysL[idx] = hl;
            }
        }
        if (t + 1 < SEQ) {
            const float* xgn = g_Xg + (long)(t + 1) * BATCH * H4 + 4 * cc;
#pragma unroll
            for (int i = 0; i < 8; ++i) {
                unsigned dst = (unsigned)__cvta_generic_to_shared(
                    &xgb[(hb * 8 + i) * XROW + 4 * cc]);
                cp16(dst, xgn + (long)gbc[i] * H4);
            }
            cp_commit();
        }
        __syncthreads();
    }
#pragma unroll
    for (int i = 0; i < 8; ++i) {
        if (vld[i]) {
            long gb = b0 + hb * 8 + i;
            hfin[gb * H + cc] = hlast[i];
            cfin[gb * H + cc] = c_reg[i];
        }
    }
}

// ---------------------------------------------------------------------------
// Tensor-core fused decoder (unchanged from R14)
// ---------------------------------------------------------------------------
#define DIROWB 112
#define DISPL  (16 * DIROWB)
#define DSMFCW (H * IN_DIM)

__global__ void __launch_bounds__(256, 1)
k_decoder_mma(const float* __restrict__ x, const float* __restrict__ fc_b,
              const ull* __restrict__ WhFH, const ull* __restrict__ WhFL,
              const ull* __restrict__ WiFH, const ull* __restrict__ WiFL,
              const ull* __restrict__ Wi0FH, const ull* __restrict__ Wi0FL,
              float* __restrict__ out) {
    extern __shared__ char smc[];
    char* hbuf = smc;
    char* dinb = smc + NL * 2 * ASPL;
    float* gates = (float*)(dinb + 2 * DISPL);
    float* fcH = gates + 16 * GST;
    float* fcw = fcH + 2048;
    float* fcb = fcw + DSMFCW;

    const int tid = threadIdx.x;
    const int w = tid >> 5, lane = tid & 31;
    const int li = lane & 7, lq = lane >> 3;
    const int aoff  = (li + (lq & 1) * 8) * AROWB + (lq >> 1) * 16;
    const int aoff2 = (li + (lq & 1) * 8) * DIROWB + (lq >> 1) * 16;
    const int ar = lane >> 2, ac = (lane & 3) * 2;
    const int cc = w * 16 + (lane & 15);
    const int hbi = lane >> 4;
    const int b0 = blockIdx.x * TBU;

    int gbc[8]; bool vld[8];
#pragma unroll
    for (int i = 0; i < 8; ++i) {
        int b = hbi * 8 + i;
        int gb = b0 + b;
        gbc[i] = gb < BATCH ? gb : BATCH - 1;
        vld[i] = (b < TBU) && (gb < BATCH);
    }
    float c_reg[NL][8];
#pragma unroll
    for (int l = 0; l < NL; ++l)
#pragma unroll
        for (int i = 0; i < 8; ++i) {
            c_reg[l][i] = g_c[((long)l * BATCH + gbc[i]) * H + cc];
            float hv = g_h[((long)l * BATCH + gbc[i]) * H + cc];
            bf16 hh, hl;
            split_bf16(hv, hh, hl);
            int b = hbi * 8 + i;
            char* hb = hbuf + l * 2 * ASPL;
            *(bf16*)(hb + b * AROWB + cc * 2) = hh;
            *(bf16*)(hb + ASPL + b * AROWB + cc * 2) = hl;
        }
    for (int i = tid; i < 16 * 48; i += 256) {
        int b = i / 48, j = i - b * 48;
        int gb = b0 + b; if (gb >= BATCH) gb = BATCH - 1;
        float v = (j < IN_DIM) ? x[((long)gb * SEQ + (SEQ - 1)) * IN_DIM + j] : 0.f;
        bf16 hh, hl;
        split_bf16(v, hh, hl);
        *(bf16*)(dinb + b * DIROWB + j * 2) = hh;
        *(bf16*)(dinb + DISPL + b * DIROWB + j * 2) = hl;
    }
    for (int i = tid; i < DSMFCW; i += 256) fcw[i] = g_fcT[i];
    for (int i = tid; i < IN_DIM; i += 256) fcb[i] = fc_b[i];

    float4 bias[NL];
#pragma unroll
    for (int l = 0; l < NL; ++l)
        bias[l] = *(const float4*)&g_decBP[l * H4 + 4 * cc];
    __syncthreads();

    const unsigned hb_s = (unsigned)__cvta_generic_to_shared(hbuf);
    const unsigned di_s = (unsigned)__cvta_generic_to_shared(dinb);

    for (int t = 0; t < TDEC; ++t) {
#pragma unroll 1
        for (int l = 0; l < NL; ++l) {
            float acc[8][4];
#pragma unroll
            for (int ni = 0; ni < 8; ++ni)
#pragma unroll
                for (int q = 0; q < 4; ++q) acc[ni][q] = 0.f;

            {
                const unsigned AbH = hb_s + l * 2 * ASPL;
                const ull* FH = WhFH + (long)l * 16384;
                const ull* FL = WhFL + (long)l * 16384;
#pragma unroll
                for (int s = 0; s < 8; ++s) {
                    uint32_t ah[4], al[4];
                    LDSM4(ah, AbH + s * 32 + aoff);
                    LDSM4(al, AbH + ASPL + s * 32 + aoff);
#pragma unroll
                    for (int ni = 0; ni < 8; ++ni) {
                        int fi = ((w * 8 + ni) * 8 + s) * 32 + lane;
                        ull bh8 = FH[fi];
                        ull bl8 = FL[fi];
                        uint32_t bh[2] = { (uint32_t)bh8, (uint32_t)(bh8 >> 32) };
                        uint32_t bl[2] = { (uint32_t)bl8, (uint32_t)(bl8 >> 32) };
                        MMA_BF16(acc[ni], ah, bh);
                        MMA_BF16(acc[ni], ah, bl);
                        MMA_BF16(acc[ni], al, bh);
                    }
                }
            }
            if (l == 0) {
#pragma unroll
                for (int s = 0; s < 3; ++s) {
                    uint32_t ah[4], al[4];
                    LDSM4(ah, di_s + s * 32 + aoff2);
                    LDSM4(al, di_s + DISPL + s * 32 + aoff2);
#pragma unroll
                    for (int ni = 0; ni < 8; ++ni) {
                        int fi = ((w * 8 + ni) * 3 + s) * 32 + lane;
                        ull bh8 = Wi0FH[fi];
                        ull bl8 = Wi0FL[fi];
                        uint32_t bh[2] = { (uint32_t)bh8, (uint32_t)(bh8 >> 32) };
                        uint32_t bl[2] = { (uint32_t)bl8, (uint32_t)(bl8 >> 32) };
                        MMA_BF16(acc[ni], ah, bh);
                        MMA_BF16(acc[ni], ah, bl);
                        MMA_BF16(acc[ni], al, bh);
                    }
                }
            } else {
                const unsigned AbH = hb_s + (l - 1) * 2 * ASPL;
                const ull* FH = WiFH + (long)(l - 1) * 16384;
                const ull* FL = WiFL + (long)(l - 1) * 16384;
#pragma unroll
                for (int s = 0; s < 8; ++s) {
                    uint32_t ah[4], al[4];
                    LDSM4(ah, AbH + s * 32 + aoff);
                    LDSM4(al, AbH + ASPL + s * 32 + aoff);
#pragma unroll
                    for (int ni = 0; ni < 8; ++ni) {
                        int fi = ((w * 8 + ni) * 8 + s) * 32 + lane;
                        ull bh8 = FH[fi];
                        ull bl8 = FL[fi];
                        uint32_t bh[2] = { (uint32_t)bh8, (uint32_t)(bh8 >> 32) };
                        uint32_t bl[2] = { (uint32_t)bl8, (uint32_t)(bl8 >> 32) };
                        MMA_BF16(acc[ni], ah, bh);
                        MMA_BF16(acc[ni], ah, bl);
                        MMA_BF16(acc[ni], al, bh);
                    }
                }
            }
#pragma unroll
            for (int ni = 0; ni < 8; ++ni) {
                int n0 = w * 64 + ni * 8 + ac;
                float2 v0 = { acc[ni][0], acc[ni][1] };
                float2 v1 = { acc[ni][2], acc[ni][3] };
                *(float2*)&gates[ar * GST + n0] = v0;
                *(float2*)&gates[(ar + 8) * GST + n0] = v1;
            }
            __syncwarp();
            char* hb = hbuf + l * 2 * ASPL;
#pragma unroll
            for (int i = 0; i < 8; ++i) {
                int b = hbi * 8 + i;
                float4 g4 = *(const float4*)&gates[b * GST + 4 * cc];
                float gi = g4.x + bias[l].x, gf = g4.y + bias[l].y;
                float gg = g4.z + bias[l].z, go = g4.w + bias[l].w;
                float cn = sigf(gf) * c_reg[l][i] + sigf(gi) * tanha(gg);
                c_reg[l][i] = cn;
                float hn = sigf(go) * tanha(cn);
                bf16 hh, hl;
                split_bf16(hn, hh, hl);
                *(bf16*)(hb + b * AROWB + cc * 2) = hh;
                *(bf16*)(hb + ASPL + b * AROWB + cc * 2) = hl;
                if (l == NL - 1) fcH[cc * 16 + b] = hn;
            }
            __syncthreads();
        }
        for (int idx = tid; idx < 16 * IN_DIM; idx += 256) {
            int b = idx / IN_DIM, j = idx - b * IN_DIM;
            float s = fcb[j];
#pragma unroll 8
            for (int k = 0; k < H; ++k)
                s += fcH[k * 16 + b] * fcw[k * IN_DIM + j];
            if (b < TBU && b0 + b < BATCH)
                out[((long)(b0 + b) * TDEC + t) * IN_DIM + j] = s;
            bf16 hh, hl;
            split_bf16(s, hh, hl);
            *(bf16*)(dinb + b * DIROWB + j * 2) = hh;
            *(bf16*)(dinb + DISPL + b * DIROWB + j * 2) = hl;
        }
        __syncthreads();
    }
}

// ---------------------------------------------------------------------------
// Host launcher
// ---------------------------------------------------------------------------
extern "C" void kernel_launch(void* const* d_in, const int* in_sizes, int n_in,
                              void* d_out, int out_size) {
    const float* x        = (const float*)d_in[0];
    const float* enc_Wih0 = (const float*)d_in[2];
    const float* enc_WihR = (const float*)d_in[3];
    const float* enc_Whh  = (const float*)d_in[4];
    const float* enc_b    = (const float*)d_in[5];
    const float* dec_Wih0 = (const float*)d_in[6];
    const float* dec_WihR = (const float*)d_in[7];
    const float* dec_Whh  = (const float*)d_in[8];
    const float* dec_b    = (const float*)d_in[9];
    const float* fc_W     = (const float*)d_in[10];
    const float* fc_b     = (const float*)d_in[11];
    float* out = (float*)d_out;

    float *encBP, *decBP, *fcT, *Xg, *hSt, *cSt;
    bf16 *W0H, *W0L, *WRH, *WRL, *ysH, *ysL, *x0H, *x0L;
    ull *eFH, *eFL, *dWhH, *dWhL, *dWiH, *dWiL, *dWi0H, *dWi0L;
    cudaGetSymbolAddress((void**)&encBP, g_encBP);
    cudaGetSymbolAddress((void**)&decBP, g_decBP);
    cudaGetSymbolAddress((void**)&fcT,   g_fcT);
    cudaGetSymbolAddress((void**)&Xg,    g_Xg);
    cudaGetSymbolAddress((void**)&hSt,   g_h);
    cudaGetSymbolAddress((void**)&cSt,   g_c);
    cudaGetSymbolAddress((void**)&W0H,   g_W0H);
    cudaGetSymbolAddress((void**)&W0L,   g_W0L);
    cudaGetSymbolAddress((void**)&WRH,   g_WRH);
    cudaGetSymbolAddress((void**)&WRL,   g_WRL);
    cudaGetSymbolAddress((void**)&ysH,   g_ysH);
    cudaGetSymbolAddress((void**)&ysL,   g_ysL);
    cudaGetSymbolAddress((void**)&x0H,   g_x0H);
    cudaGetSymbolAddress((void**)&x0L,   g_x0L);
    cudaGetSymbolAddress((void**)&eFH,   g_eWhFH);
    cudaGetSymbolAddress((void**)&eFL,   g_eWhFL);
    cudaGetSymbolAddress((void**)&dWhH,  g_dWhFH);
    cudaGetSymbolAddress((void**)&dWhL,  g_dWhFL);
    cudaGetSymbolAddress((void**)&dWiH,  g_dWiFH);
    cudaGetSymbolAddress((void**)&dWiL,  g_dWiFL);
    cudaGetSymbolAddress((void**)&dWi0H, g_dWi0FH);
    cudaGetSymbolAddress((void**)&dWi0L, g_dWi0FL);

    // GEMM smem: 2*BSP + 2*ASP2 + 640
    const int DYN48  = 2 * (128 * 112) + 2 * (64 * 112) + 640;   // 43,648
    const int DYN128 = 2 * (128 * 272) + 2 * (64 * 272) + 640;   // 105,088
    const int DECSM = NL * 2 * ASPL + 2 * DISPL + 16 * GST * 4 + 2048 * 4
                    + DSMFCW * 4 + 192;
    cudaFuncSetAttribute(k_mmagemm<48>,
                         cudaFuncAttributeMaxDynamicSharedMemorySize, DYN48);
    cudaFuncSetAttribute(k_mmagemm<128>,
                         cudaFuncAttributeMaxDynamicSharedMemorySize, DYN128);
    cudaFuncSetAttribute(k_lstm_mma<true>,
                         cudaFuncAttributeMaxDynamicSharedMemorySize, LSTM_MMA_SMEM);
    cudaFuncSetAttribute(k_lstm_mma<false>,
                         cudaFuncAttributeMaxDynamicSharedMemorySize, LSTM_MMA_SMEM);
    cudaFuncSetAttribute(k_decoder_mma,
                         cudaFuncAttributeMaxDynamicSharedMemorySize, DECSM);

    // prep (3 launches)
    {
        dim3 g(256, 5);
        k_wconv<<<g, 256>>>(enc_b, dec_b, fc_W, enc_Wih0, enc_WihR,
                            encBP, decBP, fcT, W0H, W0L, WRH, WRL);
    }
    {
        FJobs jf; jf.n = 12;
        for (int l = 0; l < NL; ++l)
            jf.j[l] = { enc_Whh + (long)l * 512 * 128, eFH + (long)l * 16384,
                        eFL + (long)l * 16384, 8, 128 };
        for (int l = 0; l < NL; ++l)
            jf.j[4 + l] = { dec_Whh + (long)l * 512 * 128, dWhH + (long)l * 16384,
                            dWhL + (long)l * 16384, 8, 128 };
        for (int r = 0; r < 3; ++r)
            jf.j[8 + r] = { dec_WihR + (long)r * 512 * 128, dWiH + (long)r * 16384,
                            dWiL + (long)r * 16384, 8, 128 };
        jf.j[11] = { dec_Wih0, dWi0H, dWi0L, 3, IN_DIM };
        dim3 g(128, 12);
        k_fragb<<<g, 256>>>(jf);
    }
    k_xconv<<<2048, 256>>>(x, x0H, x0L);

    dim3 ggrid(GBX, 4);

    // encoder layer 0
    k_mmagemm<48><<<ggrid, 256, DYN48>>>(x0H, x0L, W0H, W0L, encBP, Xg);
    k_lstm_mma<true><<<RBLK, 256, LSTM_MMA_SMEM>>>(eFH, eFL, ysH, ysL, hSt, cSt);
    // encoder layers 1..3
    for (int l = 1; l < NL; ++l) {
        k_mmagemm<128><<<ggrid, 256, DYN128>>>(
            ysH, ysL, WRH + (long)(l - 1) * 512 * 128, WRL + (long)(l - 1) * 512 * 128,
            encBP + (long)l * H4, Xg);
        if (l < NL - 1)
            k_lstm_mma<true><<<RBLK, 256, LSTM_MMA_SMEM>>>(
                eFH + (long)l * 16384, eFL + (long)l * 16384, ysH, ysL,
                hSt + (long)l * BATCH * H, cSt + (long)l * BATCH * H);
        else
            k_lstm_mma<false><<<RBLK, 256, LSTM_MMA_SMEM>>>(
                eFH + (long)l * 16384, eFL + (long)l * 16384, nullptr, nullptr,
                hSt + (long)l * BATCH * H, cSt + (long)l * BATCH * H);
    }
    // tensor-core fused decoder
    k_decoder_mma<<<RBLK, 256, DECSM>>>(x, fc_b, dWhH, dWhL, dWiH, dWiL,
                                        dWi0H, dWi0L, out);
}